// round 1
// baseline (speedup 1.0000x reference)
#include <cuda_runtime.h>

// RvNN fused kernel, fp32 with packed f32x2 FMA (Blackwell 2xFP32 path).
// One block = 16 batch elements, both tree stages fully fused in shared memory.

#define DEVINL __device__ __forceinline__
typedef unsigned long long u64;

constexpr int NTH = 512;        // threads per block (16 warps)
constexpr int BB  = 16;         // batch elements per block
// stage1: M=64 rows (16*4 positions), stage2: M=32 rows (16*2 positions)

// ---- shared memory layout (in floats) ----
constexpr int SM_UV    = 0;                   // U/V/H buffer: 64*128
constexpr int SM_CHPA  = SM_UV + 64 * 128;    // ch|pa concat: 64*512 (X staging aliases here)
constexpr int SM_WT    = SM_CHPA + 64 * 512;  // weight tile: max 16*256 = 4096
constexpr int SM_Y     = SM_WT + 4096;        // parent inputs: 64*12
constexpr int SM_S12   = SM_Y + 768;          // stage1 outputs (12 cols): 64*12
constexpr int SM_FLOATS = SM_S12 + 768;       // 46592 floats = 186368 bytes

DEVINL float sanf(float x) {
    if (isnan(x)) return 0.0f;
    if (isinf(x)) return 9999.0f;
    return x;
}

DEVINL float fast_tanh(float x) {
    // tanh(x) = sign(x) * (1 - 2/(exp(2|x|)+1)); ex2/rcp approx ~1e-7 abs err
    float ax = fabsf(x) * 2.8853900817779268f;  // 2*log2(e)
    float e; asm("ex2.approx.f32 %0, %1;" : "=f"(e) : "f"(ax));
    float r; asm("rcp.approx.f32 %0, %1;" : "=f"(r) : "f"(e + 1.0f));
    float t = fmaf(-2.0f, r, 1.0f);
    return copysignf(t, x);
}

DEVINL u64 dup2(float a) { u64 r; asm("mov.b64 %0, {%1, %1};" : "=l"(r) : "f"(a)); return r; }
DEVINL void fma2(u64& acc, u64 a, u64 b) {
    asm("fma.rn.f32x2 %0, %1, %2, %0;" : "+l"(acc) : "l"(a), "l"(b));
}
DEVINL float2 unpk(u64 v) {
    float2 r; asm("mov.b64 {%0, %1}, %2;" : "=f"(r.x), "=f"(r.y) : "l"(v)); return r;
}

// ---------- layer1: U[M][128] = prelu(A[M][KA] @ W[KA][128] + b), W fully in smem ----------
template<int M, int KA>
DEVINL void layer1(const float* __restrict__ A, const float* __restrict__ WT,
                   const float* __restrict__ bg, float alpha,
                   float* __restrict__ Uo, int tx, int ty)
{
    constexpr int RPT = M / 16;  // row-groups: ty in [0,16)
    float acc[RPT][4];
#pragma unroll
    for (int r = 0; r < RPT; r++) { acc[r][0] = acc[r][1] = acc[r][2] = acc[r][3] = 0.0f; }
    const int c0 = tx * 4;
#pragma unroll
    for (int k = 0; k < KA; k += 4) {
        float a[RPT][4];
#pragma unroll
        for (int r = 0; r < RPT; r++) {
            float4 v = *(const float4*)&A[(ty * RPT + r) * KA + k];
            a[r][0] = v.x; a[r][1] = v.y; a[r][2] = v.z; a[r][3] = v.w;
        }
#pragma unroll
        for (int j = 0; j < 4; j++) {
            float4 w = *(const float4*)&WT[(k + j) * 128 + c0];
#pragma unroll
            for (int r = 0; r < RPT; r++) {
                acc[r][0] = fmaf(a[r][j], w.x, acc[r][0]);
                acc[r][1] = fmaf(a[r][j], w.y, acc[r][1]);
                acc[r][2] = fmaf(a[r][j], w.z, acc[r][2]);
                acc[r][3] = fmaf(a[r][j], w.w, acc[r][3]);
            }
        }
    }
#pragma unroll
    for (int r = 0; r < RPT; r++) {
#pragma unroll
        for (int c = 0; c < 4; c++) {
            float v = acc[r][c] + bg[c0 + c];
            v = (v >= 0.0f) ? v : alpha * v;
            Uo[(ty * RPT + r) * 128 + c0 + c] = v;
        }
    }
}

// ---------- layer2: CHPA[M][colOff..+256] = tanh(U[M][128] @ W[128][256] + b) ----------
// packed f32x2 accumulators; thread owns col pairs {2*tx, 2*tx+1} + c2*64, c2 in [0,4)
template<int M>
DEVINL void layer2(const float* __restrict__ U, const float* __restrict__ Wg,
                   const float* __restrict__ bg, float* __restrict__ CHPA, int colOff,
                   float* __restrict__ WT, int tid, int tx, int ty)
{
    constexpr int RPT = M / 16;
    u64 acc2[RPT][4];
#pragma unroll
    for (int r = 0; r < RPT; r++)
#pragma unroll
        for (int c = 0; c < 4; c++) acc2[r][c] = 0ull;

    for (int k0 = 0; k0 < 128; k0 += 16) {
        __syncthreads();  // protect WT from previous tile's readers
        for (int i = tid; i < 16 * 256 / 4; i += NTH)
            *(float4*)&WT[i * 4] = *(const float4*)&Wg[k0 * 256 + i * 4];
        __syncthreads();
        const u64* WT2 = (const u64*)WT;  // 128 col-pairs per k-row
#pragma unroll
        for (int kk = 0; kk < 16; kk += 4) {
            float a[RPT][4];
#pragma unroll
            for (int r = 0; r < RPT; r++) {
                float4 v = *(const float4*)&U[(ty * RPT + r) * 128 + k0 + kk];
                a[r][0] = v.x; a[r][1] = v.y; a[r][2] = v.z; a[r][3] = v.w;
            }
#pragma unroll
            for (int j = 0; j < 4; j++) {
                u64 w0 = WT2[(kk + j) * 128 + tx];
                u64 w1 = WT2[(kk + j) * 128 + tx + 32];
                u64 w2 = WT2[(kk + j) * 128 + tx + 64];
                u64 w3 = WT2[(kk + j) * 128 + tx + 96];
#pragma unroll
                for (int r = 0; r < RPT; r++) {
                    u64 ad = dup2(a[r][j]);
                    fma2(acc2[r][0], ad, w0);
                    fma2(acc2[r][1], ad, w1);
                    fma2(acc2[r][2], ad, w2);
                    fma2(acc2[r][3], ad, w3);
                }
            }
        }
    }
#pragma unroll
    for (int r = 0; r < RPT; r++) {
#pragma unroll
        for (int c2 = 0; c2 < 4; c2++) {
            float2 v = unpk(acc2[r][c2]);
            int col = tx * 2 + c2 * 64;
            int row = ty * RPT + r;
            CHPA[row * 512 + colOff + col]     = fast_tanh(v.x + bg[col]);
            CHPA[row * 512 + colOff + col + 1] = fast_tanh(v.y + bg[col + 1]);
        }
    }
}

// ---------- layer3: H[M][128] = tanh(CHPA[M][512] @ Wl1[512][128] + bl1) ----------
template<int M>
DEVINL void layer3(const float* __restrict__ CHPA, const float* __restrict__ Wl1,
                   const float* __restrict__ bl1, float* __restrict__ H,
                   float* __restrict__ WT, int tid, int tx, int ty)
{
    constexpr int RPT = M / 16;
    u64 acc2[RPT][2];
#pragma unroll
    for (int r = 0; r < RPT; r++) { acc2[r][0] = 0ull; acc2[r][1] = 0ull; }

    for (int k0 = 0; k0 < 512; k0 += 32) {
        __syncthreads();
        for (int i = tid; i < 32 * 128 / 4; i += NTH)
            *(float4*)&WT[i * 4] = *(const float4*)&Wl1[k0 * 128 + i * 4];
        __syncthreads();
        const u64* WT2 = (const u64*)WT;  // 64 col-pairs per k-row
#pragma unroll
        for (int kk = 0; kk < 32; kk += 4) {
            float a[RPT][4];
#pragma unroll
            for (int r = 0; r < RPT; r++) {
                float4 v = *(const float4*)&CHPA[(ty * RPT + r) * 512 + k0 + kk];
                a[r][0] = v.x; a[r][1] = v.y; a[r][2] = v.z; a[r][3] = v.w;
            }
#pragma unroll
            for (int j = 0; j < 4; j++) {
                u64 w0 = WT2[(kk + j) * 64 + tx];
                u64 w1 = WT2[(kk + j) * 64 + tx + 32];
#pragma unroll
                for (int r = 0; r < RPT; r++) {
                    u64 ad = dup2(a[r][j]);
                    fma2(acc2[r][0], ad, w0);
                    fma2(acc2[r][1], ad, w1);
                }
            }
        }
    }
#pragma unroll
    for (int r = 0; r < RPT; r++) {
#pragma unroll
        for (int c2 = 0; c2 < 2; c2++) {
            float2 v = unpk(acc2[r][c2]);
            int col = tx * 2 + c2 * 64;
            int row = ty * RPT + r;
            H[row * 128 + col]     = fast_tanh(v.x + bl1[col]);
            H[row * 128 + col + 1] = fast_tanh(v.y + bl1[col + 1]);
        }
    }
}

// ---------- layer4: out[M][32] = prelu(H[M][128] @ Wl2[128][32] + bl2), Wl2 in smem ----------
template<int M, bool FINAL>
DEVINL void layer4(const float* __restrict__ H, const float* __restrict__ WT,
                   const float* __restrict__ bl2, float al,
                   float* __restrict__ S12, float* __restrict__ out,
                   int b0, int nb, int tx, int ty)
{
    constexpr int RPT = M / 16;
    float acc[RPT];
#pragma unroll
    for (int r = 0; r < RPT; r++) acc[r] = 0.0f;
#pragma unroll
    for (int k = 0; k < 128; k += 4) {
        float a[RPT][4];
#pragma unroll
        for (int r = 0; r < RPT; r++) {
            float4 v = *(const float4*)&H[(ty * RPT + r) * 128 + k];
            a[r][0] = v.x; a[r][1] = v.y; a[r][2] = v.z; a[r][3] = v.w;
        }
#pragma unroll
        for (int j = 0; j < 4; j++) {
            float w = WT[(k + j) * 32 + tx];
#pragma unroll
            for (int r = 0; r < RPT; r++) acc[r] = fmaf(a[r][j], w, acc[r]);
        }
    }
#pragma unroll
    for (int r = 0; r < RPT; r++) {
        float v = acc[r] + bl2[tx];
        v = (v >= 0.0f) ? v : al * v;
        int row = ty * RPT + r;
        if (FINAL) {
            int be = b0 + (row >> 1);
            if (be < nb) out[(size_t)be * 64 + (row & 1) * 32 + tx] = v;
        } else {
            if (tx < 12) S12[row * 12 + tx] = v;
        }
    }
}

// ---------- full combine() pipeline for M rows ----------
template<int M, bool FINAL>
DEVINL void pipeline(float* sm, int tid,
                     const float* Wc1, const float* bc1, float ac,
                     const float* Wc2, const float* bc2,
                     const float* Wp1, const float* bp1, float ap,
                     const float* Wp2, const float* bp2,
                     const float* Wl1, const float* bl1,
                     const float* Wl2, const float* bl2, float al,
                     float* out, int b0, int nb)
{
    float* U    = sm + SM_UV;     // also V, then H
    float* CHPA = sm + SM_CHPA;
    float* WT   = sm + SM_WT;
    float* X    = CHPA;           // X staging aliases CHPA (freed before CHPA written)
    float* Y    = sm + SM_Y;
    float* S12  = sm + SM_S12;
    const int tx = tid & 31, ty = tid >> 5;

    // A1: U = prelu(X @ Wc1 + bc1)
    for (int i = tid; i < 24 * 128; i += NTH) WT[i] = Wc1[i];
    __syncthreads();
    layer1<M, 24>(X, WT, bc1, ac, U, tx, ty);
    __syncthreads();
    // B1: ch = tanh(U @ Wc2 + bc2) -> CHPA[:, 0:256]
    layer2<M>(U, Wc2, bc2, CHPA, 0, WT, tid, tx, ty);
    __syncthreads();
    // A2: V = prelu(Y @ Wp1 + bp1) -> U region
    for (int i = tid; i < 12 * 128; i += NTH) WT[i] = Wp1[i];
    __syncthreads();
    layer1<M, 12>(Y, WT, bp1, ap, U, tx, ty);
    __syncthreads();
    // B2: pa = tanh(V @ Wp2 + bp2) -> CHPA[:, 256:512]
    layer2<M>(U, Wp2, bp2, CHPA, 256, WT, tid, tx, ty);
    __syncthreads();
    // C: h = tanh(CHPA @ Wl1 + bl1) -> U region (H)
    layer3<M>(CHPA, Wl1, bl1, U, WT, tid, tx, ty);
    __syncthreads();
    // D: out = prelu(h @ Wl2 + bl2)
    for (int i = tid; i < 128 * 32; i += NTH) WT[i] = Wl2[i];
    __syncthreads();
    layer4<M, FINAL>(U, WT, bl2, al, S12, out, b0, nb, tx, ty);
}

__global__ void __launch_bounds__(NTH, 1)
rvnn_kernel(const float* __restrict__ level1, const float* __restrict__ level2,
            const float* __restrict__ level3,
            const float* __restrict__ Wc1, const float* __restrict__ bc1, const float* __restrict__ ac,
            const float* __restrict__ Wc2, const float* __restrict__ bc2,
            const float* __restrict__ Wp1, const float* __restrict__ bp1, const float* __restrict__ ap,
            const float* __restrict__ Wp2, const float* __restrict__ bp2,
            const float* __restrict__ Wl1, const float* __restrict__ bl1,
            const float* __restrict__ Wl2, const float* __restrict__ bl2, const float* __restrict__ al,
            float* __restrict__ out, int nb)
{
    extern __shared__ float sm[];
    const int tid = threadIdx.x;
    const int b0 = blockIdx.x * BB;
    const float acv = *ac, apv = *ap, alv = *al;

    float* X   = sm + SM_CHPA;
    float* Y   = sm + SM_Y;
    float* S12 = sm + SM_S12;

    // ---- stage 1 input staging ----
    // children = pair-reversed level3: X[row=be*4+p][0:12]=c_{2p+1}, [12:24]=c_{2p}
    {
        const float* src = level3 + (size_t)b0 * 96;
        int lim = (nb - b0 < BB ? nb - b0 : BB) * 96;
        for (int i = tid; i < BB * 96; i += NTH) {
            float v = (i < lim) ? sanf(src[i]) : 0.0f;
            int be = i / 96, rem = i % 96, c = rem / 12, k = rem % 12;
            int p = c >> 1, s = c & 1;
            X[(be * 4 + p) * 24 + (1 - s) * 12 + k] = v;
        }
    }
    {
        const float* src = level2 + (size_t)b0 * 48;
        int lim = (nb - b0 < BB ? nb - b0 : BB) * 48;
        for (int i = tid; i < BB * 48; i += NTH) {
            float v = (i < lim) ? sanf(src[i]) : 0.0f;
            int be = i / 48, rem = i % 48, p = rem / 12, k = rem % 12;
            Y[(be * 4 + p) * 12 + k] = v;
        }
    }
    __syncthreads();

    pipeline<64, false>(sm, tid, Wc1, bc1, acv, Wc2, bc2, Wp1, bp1, apv,
                        Wp2, bp2, Wl1, bl1, Wl2, bl2, alv, out, b0, nb);
    __syncthreads();

    // ---- stage 2 input staging ----
    // children = pair-reversed stage1 outputs (first 12 cols of out3)
    for (int i = tid; i < 32 * 24; i += NTH) {
        int r2 = i / 24, k24 = i % 24, be = r2 >> 1, p = r2 & 1;
        int j = 2 * p + (k24 < 12 ? 1 : 0);
        int k = (k24 < 12) ? k24 : (k24 - 12);
        X[r2 * 24 + k24] = sanf(S12[(be * 4 + j) * 12 + k]);
    }
    {
        const float* src = level1 + (size_t)b0 * 24;
        int lim = (nb - b0 < BB ? nb - b0 : BB) * 24;
        for (int i = tid; i < BB * 24; i += NTH) {
            float v = (i < lim) ? sanf(src[i]) : 0.0f;
            int be = i / 24, rem = i % 24, p = rem / 12, k = rem % 12;
            Y[(be * 2 + p) * 12 + k] = v;
        }
    }
    __syncthreads();

    pipeline<32, true>(sm, tid, Wc1, bc1, acv, Wc2, bc2, Wp1, bp1, apv,
                       Wp2, bp2, Wl1, bl1, Wl2, bl2, alv, out, b0, nb);
}

extern "C" void kernel_launch(void* const* d_in, const int* in_sizes, int n_in,
                              void* d_out, int out_size) {
    const float* level1 = (const float*)d_in[0];
    const float* level2 = (const float*)d_in[1];
    const float* level3 = (const float*)d_in[2];
    const float* Wc1 = (const float*)d_in[3];
    const float* bc1 = (const float*)d_in[4];
    const float* ac  = (const float*)d_in[5];
    const float* Wc2 = (const float*)d_in[6];
    const float* bc2 = (const float*)d_in[7];
    const float* Wp1 = (const float*)d_in[8];
    const float* bp1 = (const float*)d_in[9];
    const float* ap  = (const float*)d_in[10];
    const float* Wp2 = (const float*)d_in[11];
    const float* bp2 = (const float*)d_in[12];
    const float* Wl1 = (const float*)d_in[13];
    const float* bl1 = (const float*)d_in[14];
    const float* Wl2 = (const float*)d_in[15];
    const float* bl2 = (const float*)d_in[16];
    const float* al  = (const float*)d_in[17];
    float* out = (float*)d_out;

    int nb = in_sizes[0] / 24;  // level1 is (B, 2, 12)
    int grid = (nb + BB - 1) / BB;
    size_t smem = (size_t)SM_FLOATS * sizeof(float);  // 186368 B

    cudaFuncSetAttribute(rvnn_kernel, cudaFuncAttributeMaxDynamicSharedMemorySize, (int)smem);
    rvnn_kernel<<<grid, NTH, smem>>>(level1, level2, level3, Wc1, bc1, ac, Wc2, bc2,
                                     Wp1, bp1, ap, Wp2, bp2, Wl1, bl1, Wl2, bl2, al,
                                     out, nb);
}

// round 3
// speedup vs baseline: 1.2301x; 1.2301x over previous
#include <cuda_runtime.h>

// RvNN fused kernel v2 (re-bench; previous round was an infra container failure).
// Row-pair packed f32x2 FMA, broadcast A loads, scalar weight loads,
// cp.async double-buffered weight tiles, split-K layer3.

#define DEVINL __device__ __forceinline__
typedef unsigned long long u64;

constexpr int NTH = 512;
constexpr int BB  = 16;

// ---- shared memory layout (float offsets) ----
constexpr int SM_UP   = 0;        // U_P pair layout / H (alias): 8192 floats (32KB)
constexpr int SM_CHPA = 8192;     // CHPA_P pair layout: 32768 floats (128KB); X aliases start
constexpr int SM_WT   = 40960;    // 8192 floats (32KB): weight tiles / PART / full stages
constexpr int SM_Y    = 49152;    // 768
constexpr int SM_S12  = 49920;    // 768
constexpr int SM_TOT  = 50688;    // floats -> 202752 bytes

DEVINL float sanf(float x) {
    if (isnan(x)) return 0.0f;
    if (isinf(x)) return 9999.0f;
    return x;
}

DEVINL float fast_tanh(float x) {
    float ax = fabsf(x) * 2.8853900817779268f;  // 2*log2(e)
    float e; asm("ex2.approx.f32 %0, %1;" : "=f"(e) : "f"(ax));
    float r; asm("rcp.approx.f32 %0, %1;" : "=f"(r) : "f"(e + 1.0f));
    float t = fmaf(-2.0f, r, 1.0f);
    return copysignf(t, x);
}

DEVINL u64 dup2(float a) { u64 r; asm("mov.b64 %0, {%1, %1};" : "=l"(r) : "f"(a)); return r; }
DEVINL u64 pk2(float a, float b) { u64 r; asm("mov.b64 %0, {%1, %2};" : "=l"(r) : "f"(a), "f"(b)); return r; }
DEVINL void fma2(u64& acc, u64 a, u64 b) {
    asm("fma.rn.f32x2 %0, %1, %2, %0;" : "+l"(acc) : "l"(a), "l"(b));
}
DEVINL void addf2(u64& acc, u64 b) {
    asm("add.rn.f32x2 %0, %0, %1;" : "+l"(acc) : "l"(b));
}
DEVINL float2 unpk(u64 v) {
    float2 r; asm("mov.b64 {%0, %1}, %2;" : "=f"(r.x), "=f"(r.y) : "l"(v)); return r;
}

DEVINL void cpa16(float* dst, const float* src) {
    unsigned sa = (unsigned)__cvta_generic_to_shared(dst);
    asm volatile("cp.async.cg.shared.global [%0], [%1], 16;" :: "r"(sa), "l"(src));
}
DEVINL void cpa_commit() { asm volatile("cp.async.commit_group;"); }
DEVINL void cpa_wait()   { asm volatile("cp.async.wait_group 0;"); }
DEVINL void barg(int id) { asm volatile("bar.sync %0, 256;" :: "r"(id)); }

// ---------- layer1: A[M][KA] @ W[KA][128] + b -> prelu -> U_P pair layout ----------
// thread: cols c = tx + 32j (j<4), rows ty*RPT..+RPT. W in smem (full), A broadcast.
template<int M, int KA>
DEVINL void layer1(const float* __restrict__ A, const float* __restrict__ WT,
                   const float* __restrict__ bg, float alpha,
                   u64* __restrict__ UP, int tx, int ty)
{
    constexpr int RPT = M / 16;
    float acc[RPT][4];
#pragma unroll
    for (int r = 0; r < RPT; r++)
#pragma unroll
        for (int j = 0; j < 4; j++) acc[r][j] = 0.0f;

#pragma unroll
    for (int k = 0; k < KA; k += 4) {
        float a[RPT][4];
#pragma unroll
        for (int r = 0; r < RPT; r++) {
            float4 v = *(const float4*)&A[(ty * RPT + r) * KA + k];
            a[r][0] = v.x; a[r][1] = v.y; a[r][2] = v.z; a[r][3] = v.w;
        }
#pragma unroll
        for (int j4 = 0; j4 < 4; j4++) {
            float w[4];
#pragma unroll
            for (int j = 0; j < 4; j++) w[j] = WT[(k + j4) * 128 + tx + 32 * j];
#pragma unroll
            for (int r = 0; r < RPT; r++)
#pragma unroll
                for (int j = 0; j < 4; j++)
                    acc[r][j] = fmaf(a[r][j4], w[j], acc[r][j]);
        }
    }
#pragma unroll
    for (int i = 0; i < RPT / 2; i++) {
        int pr = ty * (RPT / 2) + i;
        int xr = (pr & 7) << 1;
#pragma unroll
        for (int j = 0; j < 4; j++) {
            int c = tx + 32 * j;
            float v0 = acc[2 * i][j] + bg[c];
            float v1 = acc[2 * i + 1][j] + bg[c];
            v0 = (v0 >= 0.0f) ? v0 : alpha * v0;
            v1 = (v1 >= 0.0f) ? v1 : alpha * v1;
            UP[pr * 128 + (c ^ xr)] = pk2(v0, v1);
        }
    }
}

// ---------- layer2: U_P[MP][128] @ W[128][256] + b -> tanh -> CHPA_P at colOff ----------
// thread: cidx = lane+32*(w&1), cols c = cidx+64j (j<4); rowpairs prg..+RP.
// W streamed in double-buffered 16k x 256 tiles via cp.async (scalar LDS.32 + dup).
template<int MP>
DEVINL void layer2(const u64* __restrict__ UP, const float* __restrict__ Wg,
                   const float* __restrict__ bg, u64* __restrict__ CP, int colOff,
                   float* __restrict__ WTb, int tid)
{
    constexpr int RP = MP / 8;
    const int lane = tid & 31, w = tid >> 5;
    const int cidx = lane + 32 * (w & 1);
    const int prg  = (w >> 1) * RP;
    int base_i[RP], xr_i[RP];
#pragma unroll
    for (int i = 0; i < RP; i++) {
        base_i[i] = (prg + i) * 128;
        xr_i[i]   = ((prg + i) & 7) << 1;
    }
    u64 acc[RP][4];
#pragma unroll
    for (int i = 0; i < RP; i++)
#pragma unroll
        for (int j = 0; j < 4; j++) acc[i][j] = 0ull;

    // preload tile 0
    for (int s = tid; s < 1024; s += NTH) cpa16(WTb + s * 4, Wg + s * 4);
    cpa_commit(); cpa_wait();
    __syncthreads();

    for (int t = 0; t < 8; t++) {
        const float* wt = WTb + (t & 1) * 4096;
        if (t + 1 < 8) {
            float* nb = WTb + ((t + 1) & 1) * 4096;
            const float* ns = Wg + (t + 1) * 4096;
            for (int s = tid; s < 1024; s += NTH) cpa16(nb + s * 4, ns + s * 4);
            cpa_commit();
        }
        const int k0 = t * 16;
#pragma unroll
        for (int kk = 0; kk < 16; kk += 2) {
            ulonglong2 A2[RP];
#pragma unroll
            for (int i = 0; i < RP; i++)
                A2[i] = *(const ulonglong2*)&UP[base_i[i] + ((k0 + kk) ^ xr_i[i])];
            u64 d0[4], d1[4];
#pragma unroll
            for (int j = 0; j < 4; j++) {
                d0[j] = dup2(wt[kk * 256 + cidx + 64 * j]);
                d1[j] = dup2(wt[(kk + 1) * 256 + cidx + 64 * j]);
            }
#pragma unroll
            for (int i = 0; i < RP; i++) {
#pragma unroll
                for (int j = 0; j < 4; j++) fma2(acc[i][j], A2[i].x, d0[j]);
#pragma unroll
                for (int j = 0; j < 4; j++) fma2(acc[i][j], A2[i].y, d1[j]);
            }
        }
        cpa_wait();
        __syncthreads();
    }
#pragma unroll
    for (int i = 0; i < RP; i++) {
        int pr = prg + i;
        int xr = (pr & 7) << 1;
#pragma unroll
        for (int j = 0; j < 4; j++) {
            int c = cidx + 64 * j;
            float2 v = unpk(acc[i][j]);
            float t0 = fast_tanh(v.x + bg[c]);
            float t1 = fast_tanh(v.y + bg[c]);
            CP[pr * 512 + ((colOff + c) ^ xr)] = pk2(t0, t1);
        }
    }
}

// ---------- layer3: CHPA_P[MP][512] @ Wl1[512][128] + b -> tanh -> H row-major ----------
// split-K: group g (256 threads) covers k in [g*256,(g+1)*256); per-group double-buffered
// tiles of 16x128; group1 dumps partials to PART, group0 reduces + epilogue.
template<int MP>
DEVINL void layer3(const u64* __restrict__ CP, const float* __restrict__ Wg,
                   const float* __restrict__ bl1, float* __restrict__ H,
                   float* __restrict__ WTb, u64* __restrict__ PART, int tid)
{
    constexpr int RP = MP / 4;
    const int lane = tid & 31, w = tid >> 5;
    const int g = w >> 3;
    const int wg = w & 7;
    const int cidx = lane + 32 * (wg & 1);
    const int prg  = (wg >> 1) * RP;
    const int barid = g + 1;
    float* myWT = WTb + g * 4096;              // 2 bufs x 2048 floats
    const float* myWg = Wg + g * 256 * 128;
    const int gtid = tid & 255;
    int base_i[RP], xr_i[RP];
#pragma unroll
    for (int i = 0; i < RP; i++) {
        base_i[i] = (prg + i) * 512;
        xr_i[i]   = ((prg + i) & 7) << 1;
    }
    u64 acc[RP][2];
#pragma unroll
    for (int i = 0; i < RP; i++) { acc[i][0] = 0ull; acc[i][1] = 0ull; }

    for (int s = gtid; s < 512; s += 256) cpa16(myWT + s * 4, myWg + s * 4);
    cpa_commit(); cpa_wait();
    barg(barid);

    for (int t = 0; t < 16; t++) {
        const float* wt = myWT + (t & 1) * 2048;
        if (t + 1 < 16) {
            float* nb = myWT + ((t + 1) & 1) * 2048;
            const float* ns = myWg + (t + 1) * 2048;
            for (int s = gtid; s < 512; s += 256) cpa16(nb + s * 4, ns + s * 4);
            cpa_commit();
        }
        const int k0 = g * 256 + t * 16;
#pragma unroll
        for (int kk = 0; kk < 16; kk += 2) {
            ulonglong2 A2[RP];
#pragma unroll
            for (int i = 0; i < RP; i++)
                A2[i] = *(const ulonglong2*)&CP[base_i[i] + ((k0 + kk) ^ xr_i[i])];
            u64 d00 = dup2(wt[kk * 128 + cidx]);
            u64 d01 = dup2(wt[kk * 128 + cidx + 64]);
            u64 d10 = dup2(wt[(kk + 1) * 128 + cidx]);
            u64 d11 = dup2(wt[(kk + 1) * 128 + cidx + 64]);
#pragma unroll
            for (int i = 0; i < RP; i++) {
                fma2(acc[i][0], A2[i].x, d00);
                fma2(acc[i][1], A2[i].x, d01);
                fma2(acc[i][0], A2[i].y, d10);
                fma2(acc[i][1], A2[i].y, d11);
            }
        }
        cpa_wait();
        barg(barid);
    }
    __syncthreads();   // both groups done; WT region reusable as PART
    if (g == 1) {
#pragma unroll
        for (int i = 0; i < RP; i++)
#pragma unroll
            for (int j = 0; j < 2; j++)
                PART[(prg + i) * 128 + cidx + 64 * j] = acc[i][j];
    }
    __syncthreads();
    if (g == 0) {
#pragma unroll
        for (int i = 0; i < RP; i++) {
            int pr = prg + i;
#pragma unroll
            for (int j = 0; j < 2; j++) {
                int c = cidx + 64 * j;
                addf2(acc[i][j], PART[pr * 128 + c]);
                float2 v = unpk(acc[i][j]);
                H[(2 * pr) * 128 + c]     = fast_tanh(v.x + bl1[c]);
                H[(2 * pr + 1) * 128 + c] = fast_tanh(v.y + bl1[c]);
            }
        }
    }
}

// ---------- layer4: H[M][128] @ Wl2[128][32] + b -> prelu -> S12 / out ----------
template<int M, bool FINAL>
DEVINL void layer4(const float* __restrict__ H, const float* __restrict__ WT,
                   const float* __restrict__ bl2, float al,
                   float* __restrict__ S12, float* __restrict__ out,
                   int b0, int nb, int tx, int ty)
{
    constexpr int RPT = M / 16;
    float acc[RPT];
#pragma unroll
    for (int r = 0; r < RPT; r++) acc[r] = 0.0f;
#pragma unroll
    for (int k = 0; k < 128; k += 4) {
        float a[RPT][4];
#pragma unroll
        for (int r = 0; r < RPT; r++) {
            float4 v = *(const float4*)&H[(ty * RPT + r) * 128 + k];
            a[r][0] = v.x; a[r][1] = v.y; a[r][2] = v.z; a[r][3] = v.w;
        }
#pragma unroll
        for (int j = 0; j < 4; j++) {
            float wv = WT[(k + j) * 32 + tx];
#pragma unroll
            for (int r = 0; r < RPT; r++) acc[r] = fmaf(a[r][j], wv, acc[r]);
        }
    }
#pragma unroll
    for (int r = 0; r < RPT; r++) {
        float v = acc[r] + bl2[tx];
        v = (v >= 0.0f) ? v : al * v;
        int row = ty * RPT + r;
        if (FINAL) {
            int be = b0 + (row >> 1);
            if (be < nb) out[(size_t)be * 64 + (row & 1) * 32 + tx] = v;
        } else {
            if (tx < 12) S12[row * 12 + tx] = v;
        }
    }
}

// ---------- full combine() pipeline for M rows ----------
template<int M, bool FINAL>
DEVINL void pipeline(float* sm, int tid,
                     const float* Wc1, const float* bc1, float ac,
                     const float* Wc2, const float* bc2,
                     const float* Wp1, const float* bp1, float ap,
                     const float* Wp2, const float* bp2,
                     const float* Wl1, const float* bl1,
                     const float* Wl2, const float* bl2, float al,
                     float* out, int b0, int nb)
{
    u64*   UP   = (u64*)(sm + SM_UP);
    u64*   CP   = (u64*)(sm + SM_CHPA);
    float* WT   = sm + SM_WT;
    float* X    = sm + SM_CHPA;   // alias (consumed before CHPA written)
    float* Y    = sm + SM_Y;
    float* S12  = sm + SM_S12;
    float* H    = sm + SM_UP;     // alias (UP dead after B2)
    u64*   PART = (u64*)(sm + SM_WT);
    const int tx = tid & 31, ty = tid >> 5;

    // A1: U_P = prelu(X @ Wc1 + bc1)
    for (int i = tid; i < 24 * 128; i += NTH) WT[i] = Wc1[i];
    __syncthreads();
    layer1<M, 24>(X, WT, bc1, ac, UP, tx, ty);
    __syncthreads();
    // B1: ch -> CHPA_P cols [0,256)
    layer2<M / 2>(UP, Wc2, bc2, CP, 0, WT, tid);
    __syncthreads();
    // A2: V_P = prelu(Y @ Wp1 + bp1) (overwrites UP)
    for (int i = tid; i < 12 * 128; i += NTH) WT[i] = Wp1[i];
    __syncthreads();
    layer1<M, 12>(Y, WT, bp1, ap, UP, tx, ty);
    __syncthreads();
    // B2: pa -> CHPA_P cols [256,512)
    layer2<M / 2>(UP, Wp2, bp2, CP, 256, WT, tid);
    __syncthreads();
    // C: h = tanh(CHPA_P @ Wl1 + bl1) -> H (row-major, aliases UP)
    layer3<M / 2>(CP, Wl1, bl1, H, WT, PART, tid);
    __syncthreads();
    // D: out = prelu(h @ Wl2 + bl2)
    for (int i = tid; i < 128 * 32; i += NTH) WT[i] = Wl2[i];
    __syncthreads();
    layer4<M, FINAL>(H, WT, bl2, al, S12, out, b0, nb, tx, ty);
}

__global__ void __launch_bounds__(NTH, 1)
rvnn_kernel(const float* __restrict__ level1, const float* __restrict__ level2,
            const float* __restrict__ level3,
            const float* __restrict__ Wc1, const float* __restrict__ bc1, const float* __restrict__ ac,
            const float* __restrict__ Wc2, const float* __restrict__ bc2,
            const float* __restrict__ Wp1, const float* __restrict__ bp1, const float* __restrict__ ap,
            const float* __restrict__ Wp2, const float* __restrict__ bp2,
            const float* __restrict__ Wl1, const float* __restrict__ bl1,
            const float* __restrict__ Wl2, const float* __restrict__ bl2, const float* __restrict__ al,
            float* __restrict__ out, int nb)
{
    extern __shared__ float sm[];
    const int tid = threadIdx.x;
    const int b0 = blockIdx.x * BB;
    const float acv = *ac, apv = *ap, alv = *al;

    float* X   = sm + SM_CHPA;
    float* Y   = sm + SM_Y;
    float* S12 = sm + SM_S12;

    // ---- stage 1 input staging ----
    {
        const float* src = level3 + (size_t)b0 * 96;
        int lim = (nb - b0 < BB ? nb - b0 : BB) * 96;
        for (int i = tid; i < BB * 96; i += NTH) {
            float v = (i < lim) ? sanf(src[i]) : 0.0f;
            int be = i / 96, rem = i % 96, c = rem / 12, k = rem % 12;
            int p = c >> 1, s = c & 1;
            X[(be * 4 + p) * 24 + (1 - s) * 12 + k] = v;
        }
    }
    {
        const float* src = level2 + (size_t)b0 * 48;
        int lim = (nb - b0 < BB ? nb - b0 : BB) * 48;
        for (int i = tid; i < BB * 48; i += NTH) {
            float v = (i < lim) ? sanf(src[i]) : 0.0f;
            int be = i / 48, rem = i % 48, p = rem / 12, k = rem % 12;
            Y[(be * 4 + p) * 12 + k] = v;
        }
    }
    __syncthreads();

    pipeline<64, false>(sm, tid, Wc1, bc1, acv, Wc2, bc2, Wp1, bp1, apv,
                        Wp2, bp2, Wl1, bl1, Wl2, bl2, alv, out, b0, nb);
    __syncthreads();

    // ---- stage 2 input staging ----
    for (int i = tid; i < 32 * 24; i += NTH) {
        int r2 = i / 24, k24 = i % 24, be = r2 >> 1, p = r2 & 1;
        int j = 2 * p + (k24 < 12 ? 1 : 0);
        int k = (k24 < 12) ? k24 : (k24 - 12);
        X[r2 * 24 + k24] = sanf(S12[(be * 4 + j) * 12 + k]);
    }
    {
        const float* src = level1 + (size_t)b0 * 24;
        int lim = (nb - b0 < BB ? nb - b0 : BB) * 24;
        for (int i = tid; i < BB * 24; i += NTH) {
            float v = (i < lim) ? sanf(src[i]) : 0.0f;
            int be = i / 24, rem = i % 24, p = rem / 12, k = rem % 12;
            Y[(be * 2 + p) * 12 + k] = v;
        }
    }
    __syncthreads();

    pipeline<32, true>(sm, tid, Wc1, bc1, acv, Wc2, bc2, Wp1, bp1, apv,
                       Wp2, bp2, Wl1, bl1, Wl2, bl2, alv, out, b0, nb);
}

extern "C" void kernel_launch(void* const* d_in, const int* in_sizes, int n_in,
                              void* d_out, int out_size) {
    const float* level1 = (const float*)d_in[0];
    const float* level2 = (const float*)d_in[1];
    const float* level3 = (const float*)d_in[2];
    const float* Wc1 = (const float*)d_in[3];
    const float* bc1 = (const float*)d_in[4];
    const float* ac  = (const float*)d_in[5];
    const float* Wc2 = (const float*)d_in[6];
    const float* bc2 = (const float*)d_in[7];
    const float* Wp1 = (const float*)d_in[8];
    const float* bp1 = (const float*)d_in[9];
    const float* ap  = (const float*)d_in[10];
    const float* Wp2 = (const float*)d_in[11];
    const float* bp2 = (const float*)d_in[12];
    const float* Wl1 = (const float*)d_in[13];
    const float* bl1 = (const float*)d_in[14];
    const float* Wl2 = (const float*)d_in[15];
    const float* bl2 = (const float*)d_in[16];
    const float* al  = (const float*)d_in[17];
    float* out = (float*)d_out;

    int nb = in_sizes[0] / 24;
    int grid = (nb + BB - 1) / BB;
    size_t smem = (size_t)SM_TOT * sizeof(float);  // 202752 B

    cudaFuncSetAttribute(rvnn_kernel, cudaFuncAttributeMaxDynamicSharedMemorySize, (int)smem);
    rvnn_kernel<<<grid, NTH, smem>>>(level1, level2, level3, Wc1, bc1, ac, Wc2, bc2,
                                     Wp1, bp1, ap, Wp2, bp2, Wl1, bl1, Wl2, bl2, al,
                                     out, nb);
}

// round 4
// speedup vs baseline: 1.2318x; 1.0014x over previous
#include <cuda_runtime.h>

// RvNN fused kernel v2 (re-bench; previous round was an infra container failure).
// Row-pair packed f32x2 FMA, broadcast A loads, scalar weight loads,
// cp.async double-buffered weight tiles, split-K layer3.

#define DEVINL __device__ __forceinline__
typedef unsigned long long u64;

constexpr int NTH = 512;
constexpr int BB  = 16;

// ---- shared memory layout (float offsets) ----
constexpr int SM_UP   = 0;        // U_P pair layout / H (alias): 8192 floats (32KB)
constexpr int SM_CHPA = 8192;     // CHPA_P pair layout: 32768 floats (128KB); X aliases start
constexpr int SM_WT   = 40960;    // 8192 floats (32KB): weight tiles / PART / full stages
constexpr int SM_Y    = 49152;    // 768
constexpr int SM_S12  = 49920;    // 768
constexpr int SM_TOT  = 50688;    // floats -> 202752 bytes

DEVINL float sanf(float x) {
    if (isnan(x)) return 0.0f;
    if (isinf(x)) return 9999.0f;
    return x;
}

DEVINL float fast_tanh(float x) {
    float ax = fabsf(x) * 2.8853900817779268f;  // 2*log2(e)
    float e; asm("ex2.approx.f32 %0, %1;" : "=f"(e) : "f"(ax));
    float r; asm("rcp.approx.f32 %0, %1;" : "=f"(r) : "f"(e + 1.0f));
    float t = fmaf(-2.0f, r, 1.0f);
    return copysignf(t, x);
}

DEVINL u64 dup2(float a) { u64 r; asm("mov.b64 %0, {%1, %1};" : "=l"(r) : "f"(a)); return r; }
DEVINL u64 pk2(float a, float b) { u64 r; asm("mov.b64 %0, {%1, %2};" : "=l"(r) : "f"(a), "f"(b)); return r; }
DEVINL void fma2(u64& acc, u64 a, u64 b) {
    asm("fma.rn.f32x2 %0, %1, %2, %0;" : "+l"(acc) : "l"(a), "l"(b));
}
DEVINL void addf2(u64& acc, u64 b) {
    asm("add.rn.f32x2 %0, %0, %1;" : "+l"(acc) : "l"(b));
}
DEVINL float2 unpk(u64 v) {
    float2 r; asm("mov.b64 {%0, %1}, %2;" : "=f"(r.x), "=f"(r.y) : "l"(v)); return r;
}

DEVINL void cpa16(float* dst, const float* src) {
    unsigned sa = (unsigned)__cvta_generic_to_shared(dst);
    asm volatile("cp.async.cg.shared.global [%0], [%1], 16;" :: "r"(sa), "l"(src));
}
DEVINL void cpa_commit() { asm volatile("cp.async.commit_group;"); }
DEVINL void cpa_wait()   { asm volatile("cp.async.wait_group 0;"); }
DEVINL void barg(int id) { asm volatile("bar.sync %0, 256;" :: "r"(id)); }

// ---------- layer1: A[M][KA] @ W[KA][128] + b -> prelu -> U_P pair layout ----------
// thread: cols c = tx + 32j (j<4), rows ty*RPT..+RPT. W in smem (full), A broadcast.
template<int M, int KA>
DEVINL void layer1(const float* __restrict__ A, const float* __restrict__ WT,
                   const float* __restrict__ bg, float alpha,
                   u64* __restrict__ UP, int tx, int ty)
{
    constexpr int RPT = M / 16;
    float acc[RPT][4];
#pragma unroll
    for (int r = 0; r < RPT; r++)
#pragma unroll
        for (int j = 0; j < 4; j++) acc[r][j] = 0.0f;

#pragma unroll
    for (int k = 0; k < KA; k += 4) {
        float a[RPT][4];
#pragma unroll
        for (int r = 0; r < RPT; r++) {
            float4 v = *(const float4*)&A[(ty * RPT + r) * KA + k];
            a[r][0] = v.x; a[r][1] = v.y; a[r][2] = v.z; a[r][3] = v.w;
        }
#pragma unroll
        for (int j4 = 0; j4 < 4; j4++) {
            float w[4];
#pragma unroll
            for (int j = 0; j < 4; j++) w[j] = WT[(k + j4) * 128 + tx + 32 * j];
#pragma unroll
            for (int r = 0; r < RPT; r++)
#pragma unroll
                for (int j = 0; j < 4; j++)
                    acc[r][j] = fmaf(a[r][j4], w[j], acc[r][j]);
        }
    }
#pragma unroll
    for (int i = 0; i < RPT / 2; i++) {
        int pr = ty * (RPT / 2) + i;
        int xr = (pr & 7) << 1;
#pragma unroll
        for (int j = 0; j < 4; j++) {
            int c = tx + 32 * j;
            float v0 = acc[2 * i][j] + bg[c];
            float v1 = acc[2 * i + 1][j] + bg[c];
            v0 = (v0 >= 0.0f) ? v0 : alpha * v0;
            v1 = (v1 >= 0.0f) ? v1 : alpha * v1;
            UP[pr * 128 + (c ^ xr)] = pk2(v0, v1);
        }
    }
}

// ---------- layer2: U_P[MP][128] @ W[128][256] + b -> tanh -> CHPA_P at colOff ----------
// thread: cidx = lane+32*(w&1), cols c = cidx+64j (j<4); rowpairs prg..+RP.
// W streamed in double-buffered 16k x 256 tiles via cp.async (scalar LDS.32 + dup).
template<int MP>
DEVINL void layer2(const u64* __restrict__ UP, const float* __restrict__ Wg,
                   const float* __restrict__ bg, u64* __restrict__ CP, int colOff,
                   float* __restrict__ WTb, int tid)
{
    constexpr int RP = MP / 8;
    const int lane = tid & 31, w = tid >> 5;
    const int cidx = lane + 32 * (w & 1);
    const int prg  = (w >> 1) * RP;
    int base_i[RP], xr_i[RP];
#pragma unroll
    for (int i = 0; i < RP; i++) {
        base_i[i] = (prg + i) * 128;
        xr_i[i]   = ((prg + i) & 7) << 1;
    }
    u64 acc[RP][4];
#pragma unroll
    for (int i = 0; i < RP; i++)
#pragma unroll
        for (int j = 0; j < 4; j++) acc[i][j] = 0ull;

    // preload tile 0
    for (int s = tid; s < 1024; s += NTH) cpa16(WTb + s * 4, Wg + s * 4);
    cpa_commit(); cpa_wait();
    __syncthreads();

    for (int t = 0; t < 8; t++) {
        const float* wt = WTb + (t & 1) * 4096;
        if (t + 1 < 8) {
            float* nb = WTb + ((t + 1) & 1) * 4096;
            const float* ns = Wg + (t + 1) * 4096;
            for (int s = tid; s < 1024; s += NTH) cpa16(nb + s * 4, ns + s * 4);
            cpa_commit();
        }
        const int k0 = t * 16;
#pragma unroll
        for (int kk = 0; kk < 16; kk += 2) {
            ulonglong2 A2[RP];
#pragma unroll
            for (int i = 0; i < RP; i++)
                A2[i] = *(const ulonglong2*)&UP[base_i[i] + ((k0 + kk) ^ xr_i[i])];
            u64 d0[4], d1[4];
#pragma unroll
            for (int j = 0; j < 4; j++) {
                d0[j] = dup2(wt[kk * 256 + cidx + 64 * j]);
                d1[j] = dup2(wt[(kk + 1) * 256 + cidx + 64 * j]);
            }
#pragma unroll
            for (int i = 0; i < RP; i++) {
#pragma unroll
                for (int j = 0; j < 4; j++) fma2(acc[i][j], A2[i].x, d0[j]);
#pragma unroll
                for (int j = 0; j < 4; j++) fma2(acc[i][j], A2[i].y, d1[j]);
            }
        }
        cpa_wait();
        __syncthreads();
    }
#pragma unroll
    for (int i = 0; i < RP; i++) {
        int pr = prg + i;
        int xr = (pr & 7) << 1;
#pragma unroll
        for (int j = 0; j < 4; j++) {
            int c = cidx + 64 * j;
            float2 v = unpk(acc[i][j]);
            float t0 = fast_tanh(v.x + bg[c]);
            float t1 = fast_tanh(v.y + bg[c]);
            CP[pr * 512 + ((colOff + c) ^ xr)] = pk2(t0, t1);
        }
    }
}

// ---------- layer3: CHPA_P[MP][512] @ Wl1[512][128] + b -> tanh -> H row-major ----------
// split-K: group g (256 threads) covers k in [g*256,(g+1)*256); per-group double-buffered
// tiles of 16x128; group1 dumps partials to PART, group0 reduces + epilogue.
template<int MP>
DEVINL void layer3(const u64* __restrict__ CP, const float* __restrict__ Wg,
                   const float* __restrict__ bl1, float* __restrict__ H,
                   float* __restrict__ WTb, u64* __restrict__ PART, int tid)
{
    constexpr int RP = MP / 4;
    const int lane = tid & 31, w = tid >> 5;
    const int g = w >> 3;
    const int wg = w & 7;
    const int cidx = lane + 32 * (wg & 1);
    const int prg  = (wg >> 1) * RP;
    const int barid = g + 1;
    float* myWT = WTb + g * 4096;              // 2 bufs x 2048 floats
    const float* myWg = Wg + g * 256 * 128;
    const int gtid = tid & 255;
    int base_i[RP], xr_i[RP];
#pragma unroll
    for (int i = 0; i < RP; i++) {
        base_i[i] = (prg + i) * 512;
        xr_i[i]   = ((prg + i) & 7) << 1;
    }
    u64 acc[RP][2];
#pragma unroll
    for (int i = 0; i < RP; i++) { acc[i][0] = 0ull; acc[i][1] = 0ull; }

    for (int s = gtid; s < 512; s += 256) cpa16(myWT + s * 4, myWg + s * 4);
    cpa_commit(); cpa_wait();
    barg(barid);

    for (int t = 0; t < 16; t++) {
        const float* wt = myWT + (t & 1) * 2048;
        if (t + 1 < 16) {
            float* nb = myWT + ((t + 1) & 1) * 2048;
            const float* ns = myWg + (t + 1) * 2048;
            for (int s = gtid; s < 512; s += 256) cpa16(nb + s * 4, ns + s * 4);
            cpa_commit();
        }
        const int k0 = g * 256 + t * 16;
#pragma unroll
        for (int kk = 0; kk < 16; kk += 2) {
            ulonglong2 A2[RP];
#pragma unroll
            for (int i = 0; i < RP; i++)
                A2[i] = *(const ulonglong2*)&CP[base_i[i] + ((k0 + kk) ^ xr_i[i])];
            u64 d00 = dup2(wt[kk * 128 + cidx]);
            u64 d01 = dup2(wt[kk * 128 + cidx + 64]);
            u64 d10 = dup2(wt[(kk + 1) * 128 + cidx]);
            u64 d11 = dup2(wt[(kk + 1) * 128 + cidx + 64]);
#pragma unroll
            for (int i = 0; i < RP; i++) {
                fma2(acc[i][0], A2[i].x, d00);
                fma2(acc[i][1], A2[i].x, d01);
                fma2(acc[i][0], A2[i].y, d10);
                fma2(acc[i][1], A2[i].y, d11);
            }
        }
        cpa_wait();
        barg(barid);
    }
    __syncthreads();   // both groups done; WT region reusable as PART
    if (g == 1) {
#pragma unroll
        for (int i = 0; i < RP; i++)
#pragma unroll
            for (int j = 0; j < 2; j++)
                PART[(prg + i) * 128 + cidx + 64 * j] = acc[i][j];
    }
    __syncthreads();
    if (g == 0) {
#pragma unroll
        for (int i = 0; i < RP; i++) {
            int pr = prg + i;
#pragma unroll
            for (int j = 0; j < 2; j++) {
                int c = cidx + 64 * j;
                addf2(acc[i][j], PART[pr * 128 + c]);
                float2 v = unpk(acc[i][j]);
                H[(2 * pr) * 128 + c]     = fast_tanh(v.x + bl1[c]);
                H[(2 * pr + 1) * 128 + c] = fast_tanh(v.y + bl1[c]);
            }
        }
    }
}

// ---------- layer4: H[M][128] @ Wl2[128][32] + b -> prelu -> S12 / out ----------
template<int M, bool FINAL>
DEVINL void layer4(const float* __restrict__ H, const float* __restrict__ WT,
                   const float* __restrict__ bl2, float al,
                   float* __restrict__ S12, float* __restrict__ out,
                   int b0, int nb, int tx, int ty)
{
    constexpr int RPT = M / 16;
    float acc[RPT];
#pragma unroll
    for (int r = 0; r < RPT; r++) acc[r] = 0.0f;
#pragma unroll
    for (int k = 0; k < 128; k += 4) {
        float a[RPT][4];
#pragma unroll
        for (int r = 0; r < RPT; r++) {
            float4 v = *(const float4*)&H[(ty * RPT + r) * 128 + k];
            a[r][0] = v.x; a[r][1] = v.y; a[r][2] = v.z; a[r][3] = v.w;
        }
#pragma unroll
        for (int j = 0; j < 4; j++) {
            float wv = WT[(k + j) * 32 + tx];
#pragma unroll
            for (int r = 0; r < RPT; r++) acc[r] = fmaf(a[r][j], wv, acc[r]);
        }
    }
#pragma unroll
    for (int r = 0; r < RPT; r++) {
        float v = acc[r] + bl2[tx];
        v = (v >= 0.0f) ? v : al * v;
        int row = ty * RPT + r;
        if (FINAL) {
            int be = b0 + (row >> 1);
            if (be < nb) out[(size_t)be * 64 + (row & 1) * 32 + tx] = v;
        } else {
            if (tx < 12) S12[row * 12 + tx] = v;
        }
    }
}

// ---------- full combine() pipeline for M rows ----------
template<int M, bool FINAL>
DEVINL void pipeline(float* sm, int tid,
                     const float* Wc1, const float* bc1, float ac,
                     const float* Wc2, const float* bc2,
                     const float* Wp1, const float* bp1, float ap,
                     const float* Wp2, const float* bp2,
                     const float* Wl1, const float* bl1,
                     const float* Wl2, const float* bl2, float al,
                     float* out, int b0, int nb)
{
    u64*   UP   = (u64*)(sm + SM_UP);
    u64*   CP   = (u64*)(sm + SM_CHPA);
    float* WT   = sm + SM_WT;
    float* X    = sm + SM_CHPA;   // alias (consumed before CHPA written)
    float* Y    = sm + SM_Y;
    float* S12  = sm + SM_S12;
    float* H    = sm + SM_UP;     // alias (UP dead after B2)
    u64*   PART = (u64*)(sm + SM_WT);
    const int tx = tid & 31, ty = tid >> 5;

    // A1: U_P = prelu(X @ Wc1 + bc1)
    for (int i = tid; i < 24 * 128; i += NTH) WT[i] = Wc1[i];
    __syncthreads();
    layer1<M, 24>(X, WT, bc1, ac, UP, tx, ty);
    __syncthreads();
    // B1: ch -> CHPA_P cols [0,256)
    layer2<M / 2>(UP, Wc2, bc2, CP, 0, WT, tid);
    __syncthreads();
    // A2: V_P = prelu(Y @ Wp1 + bp1) (overwrites UP)
    for (int i = tid; i < 12 * 128; i += NTH) WT[i] = Wp1[i];
    __syncthreads();
    layer1<M, 12>(Y, WT, bp1, ap, UP, tx, ty);
    __syncthreads();
    // B2: pa -> CHPA_P cols [256,512)
    layer2<M / 2>(UP, Wp2, bp2, CP, 256, WT, tid);
    __syncthreads();
    // C: h = tanh(CHPA_P @ Wl1 + bl1) -> H (row-major, aliases UP)
    layer3<M / 2>(CP, Wl1, bl1, H, WT, PART, tid);
    __syncthreads();
    // D: out = prelu(h @ Wl2 + bl2)
    for (int i = tid; i < 128 * 32; i += NTH) WT[i] = Wl2[i];
    __syncthreads();
    layer4<M, FINAL>(H, WT, bl2, al, S12, out, b0, nb, tx, ty);
}

__global__ void __launch_bounds__(NTH, 1)
rvnn_kernel(const float* __restrict__ level1, const float* __restrict__ level2,
            const float* __restrict__ level3,
            const float* __restrict__ Wc1, const float* __restrict__ bc1, const float* __restrict__ ac,
            const float* __restrict__ Wc2, const float* __restrict__ bc2,
            const float* __restrict__ Wp1, const float* __restrict__ bp1, const float* __restrict__ ap,
            const float* __restrict__ Wp2, const float* __restrict__ bp2,
            const float* __restrict__ Wl1, const float* __restrict__ bl1,
            const float* __restrict__ Wl2, const float* __restrict__ bl2, const float* __restrict__ al,
            float* __restrict__ out, int nb)
{
    extern __shared__ float sm[];
    const int tid = threadIdx.x;
    const int b0 = blockIdx.x * BB;
    const float acv = *ac, apv = *ap, alv = *al;

    float* X   = sm + SM_CHPA;
    float* Y   = sm + SM_Y;
    float* S12 = sm + SM_S12;

    // ---- stage 1 input staging ----
    {
        const float* src = level3 + (size_t)b0 * 96;
        int lim = (nb - b0 < BB ? nb - b0 : BB) * 96;
        for (int i = tid; i < BB * 96; i += NTH) {
            float v = (i < lim) ? sanf(src[i]) : 0.0f;
            int be = i / 96, rem = i % 96, c = rem / 12, k = rem % 12;
            int p = c >> 1, s = c & 1;
            X[(be * 4 + p) * 24 + (1 - s) * 12 + k] = v;
        }
    }
    {
        const float* src = level2 + (size_t)b0 * 48;
        int lim = (nb - b0 < BB ? nb - b0 : BB) * 48;
        for (int i = tid; i < BB * 48; i += NTH) {
            float v = (i < lim) ? sanf(src[i]) : 0.0f;
            int be = i / 48, rem = i % 48, p = rem / 12, k = rem % 12;
            Y[(be * 4 + p) * 12 + k] = v;
        }
    }
    __syncthreads();

    pipeline<64, false>(sm, tid, Wc1, bc1, acv, Wc2, bc2, Wp1, bp1, apv,
                        Wp2, bp2, Wl1, bl1, Wl2, bl2, alv, out, b0, nb);
    __syncthreads();

    // ---- stage 2 input staging ----
    for (int i = tid; i < 32 * 24; i += NTH) {
        int r2 = i / 24, k24 = i % 24, be = r2 >> 1, p = r2 & 1;
        int j = 2 * p + (k24 < 12 ? 1 : 0);
        int k = (k24 < 12) ? k24 : (k24 - 12);
        X[r2 * 24 + k24] = sanf(S12[(be * 4 + j) * 12 + k]);
    }
    {
        const float* src = level1 + (size_t)b0 * 24;
        int lim = (nb - b0 < BB ? nb - b0 : BB) * 24;
        for (int i = tid; i < BB * 24; i += NTH) {
            float v = (i < lim) ? sanf(src[i]) : 0.0f;
            int be = i / 24, rem = i % 24, p = rem / 12, k = rem % 12;
            Y[(be * 2 + p) * 12 + k] = v;
        }
    }
    __syncthreads();

    pipeline<32, true>(sm, tid, Wc1, bc1, acv, Wc2, bc2, Wp1, bp1, apv,
                       Wp2, bp2, Wl1, bl1, Wl2, bl2, alv, out, b0, nb);
}

extern "C" void kernel_launch(void* const* d_in, const int* in_sizes, int n_in,
                              void* d_out, int out_size) {
    const float* level1 = (const float*)d_in[0];
    const float* level2 = (const float*)d_in[1];
    const float* level3 = (const float*)d_in[2];
    const float* Wc1 = (const float*)d_in[3];
    const float* bc1 = (const float*)d_in[4];
    const float* ac  = (const float*)d_in[5];
    const float* Wc2 = (const float*)d_in[6];
    const float* bc2 = (const float*)d_in[7];
    const float* Wp1 = (const float*)d_in[8];
    const float* bp1 = (const float*)d_in[9];
    const float* ap  = (const float*)d_in[10];
    const float* Wp2 = (const float*)d_in[11];
    const float* bp2 = (const float*)d_in[12];
    const float* Wl1 = (const float*)d_in[13];
    const float* bl1 = (const float*)d_in[14];
    const float* Wl2 = (const float*)d_in[15];
    const float* bl2 = (const float*)d_in[16];
    const float* al  = (const float*)d_in[17];
    float* out = (float*)d_out;

    int nb = in_sizes[0] / 24;
    int grid = (nb + BB - 1) / BB;
    size_t smem = (size_t)SM_TOT * sizeof(float);  // 202752 B

    cudaFuncSetAttribute(rvnn_kernel, cudaFuncAttributeMaxDynamicSharedMemorySize, (int)smem);
    rvnn_kernel<<<grid, NTH, smem>>>(level1, level2, level3, Wc1, bc1, ac, Wc2, bc2,
                                     Wp1, bp1, ap, Wp2, bp2, Wl1, bl1, Wl2, bl2, al,
                                     out, nb);
}